// round 8
// baseline (speedup 1.0000x reference)
#include <cuda_runtime.h>

#define NUM_GRAPHS 512
#define D 128
#define H 256
#define GPB 4             // graphs per MLP block
#define MLP_T 1024        // 256 cols x 4 K-quarters

#define SEG_T   256       // segsum threads/block (8 warps)
#define SEG_RPW 32        // rows per warp (4 batches of 8)
#define SEG_RPB 256       // rows per block

// Scratch (allocation-free rule): zero-initialized at load; mlp_kernel
// re-zeroes its slice after consumption so each graph replay starts clean.
__device__ float g_S[NUM_GRAPHS * D];

// ---------------------------------------------------------------------------
__device__ __forceinline__ void facc(float4& a, float4 v) {
    a.x += v.x; a.y += v.y; a.z += v.z; a.w += v.w;
}
__device__ __forceinline__ void flush_acc(int g, int lane, float4 a) {
    float* p = &g_S[g * D + lane * 4];
    atomicAdd(p + 0, a.x);
    atomicAdd(p + 1, a.y);
    atomicAdd(p + 2, a.z);
    atomicAdd(p + 3, a.w);
}

// Segment sum over sorted batch. Warp owns 32 contiguous rows; lane owns one
// float4 column chunk. Single-graph windows (84%): 4 batches of 8 independent
// LDG.128 into 4 accumulators, ONE atomic flush per warp.
__global__ __launch_bounds__(SEG_T, 4) void segsum_kernel(
        const float4* __restrict__ x4, const int* __restrict__ batch, int N) {
    __shared__ int sb[SEG_RPB];
    const int t = threadIdx.x;
    const int blockStart = blockIdx.x * SEG_RPB;
    const int rows = min(N - blockStart, SEG_RPB);

    if (t < rows) sb[t] = batch[blockStart + t];
    __syncthreads();

    const int lane = t & 31;
    const int warp = t >> 5;
    const int r0 = warp * SEG_RPW;
    if (r0 >= rows) return;
    const int r1 = min(r0 + SEG_RPW, rows);

    const float4* xp = x4 + (size_t)blockStart * (D / 4) + lane;

    const int gF = sb[r0];
    const int gL = sb[r1 - 1];

    if (gF == gL && r1 - r0 == SEG_RPW) {
        // Uniform full window: 4 x (8 independent loads) -> 4 accs, 1 flush.
        float4 a0 = make_float4(0.f, 0.f, 0.f, 0.f);
        float4 a1 = a0, a2 = a0, a3 = a0;
        #pragma unroll
        for (int k = 0; k < SEG_RPW; k += 8) {
            float4 v0 = xp[(size_t)(r0 + k + 0) * (D / 4)];
            float4 v1 = xp[(size_t)(r0 + k + 1) * (D / 4)];
            float4 v2 = xp[(size_t)(r0 + k + 2) * (D / 4)];
            float4 v3 = xp[(size_t)(r0 + k + 3) * (D / 4)];
            float4 v4 = xp[(size_t)(r0 + k + 4) * (D / 4)];
            float4 v5 = xp[(size_t)(r0 + k + 5) * (D / 4)];
            float4 v6 = xp[(size_t)(r0 + k + 6) * (D / 4)];
            float4 v7 = xp[(size_t)(r0 + k + 7) * (D / 4)];
            facc(a0, v0); facc(a1, v1); facc(a2, v2); facc(a3, v3);
            facc(a0, v4); facc(a1, v5); facc(a2, v6); facc(a3, v7);
        }
        facc(a0, a1); facc(a2, a3); facc(a0, a2);
        flush_acc(gF, lane, a0);
    } else if (gF == gL) {
        // Uniform partial window (block tail).
        float4 a = make_float4(0.f, 0.f, 0.f, 0.f);
        for (int i = r0; i < r1; i++) facc(a, xp[(size_t)i * (D / 4)]);
        flush_acc(gF, lane, a);
    } else {
        // Window spans >=2 graphs: run-length loop, flush per run.
        float4 acc = make_float4(0.f, 0.f, 0.f, 0.f);
        int cur = gF;
        for (int i = r0; i < r1; i++) {
            int g = sb[i];
            float4 v = xp[(size_t)i * (D / 4)];
            if (g != cur) {
                flush_acc(cur, lane, acc);
                cur = g;
                acc = v;
            } else {
                facc(acc, v);
            }
        }
        flush_acc(cur, lane, acc);
    }
}

// ---------------------------------------------------------------------------
__device__ __forceinline__ int warp_lower_bound(const int* __restrict__ a,
                                                int n, int v, int lane) {
    int lo = 0, hi = n;
    while (hi - lo > 32) {
        int span = hi - lo;
        int idx = lo + (int)(((long long)span * lane) >> 5);
        int av = a[idx];
        unsigned m = __ballot_sync(0xFFFFFFFFu, av < v);
        int c = __popc(m);
        int nlo = (c > 0) ? lo + (int)(((long long)span * (c - 1)) >> 5) + 1 : lo;
        int nhi = (c < 32) ? lo + (int)(((long long)span * c) >> 5) : hi;
        lo = nlo; hi = nhi;
    }
    int idx = lo + lane;
    bool lt = (idx < hi) ? (a[idx] < v) : false;
    unsigned m = __ballot_sync(0xFFFFFFFFu, lt);
    return lo + __popc(m);
}

// Per-graph MLP + fused scatter + g_S re-zero.
// 1024 threads: col = t&255, K-quarter qr = t>>8. Weights load straight from
// gmem to registers (coalesced, 16-deep batches); activations via LDS.128;
// one partial-combine per layer.
__global__ __launch_bounds__(MLP_T) void mlp_kernel(
        const int* __restrict__ batch, int N,
        const float* __restrict__ W1, const float* __restrict__ b1,
        const float* __restrict__ W2, const float* __restrict__ b2,
        const float* __restrict__ Wc, const float* __restrict__ bc,
        float* __restrict__ out) {
    __shared__ float sS[GPB][D];
    __shared__ float sH[GPB][H];
    __shared__ float sP[4][GPB][H];
    __shared__ float sRed[GPB][8];
    __shared__ int   sbound[GPB + 1];
    __shared__ float sv[GPB];

    const int g0   = blockIdx.x * GPB;
    const int t    = threadIdx.x;
    const int col  = t & (H - 1);
    const int qr   = t >> 8;
    const int lane = t & 31;
    const int warp = t >> 5;

    if (t < GPB * D) {
        sS[t / D][t % D] = g_S[g0 * D + t];
        g_S[g0 * D + t] = 0.f;
    }
    if (warp <= GPB) {
        int r = warp_lower_bound(batch, N, g0 + warp, lane);
        if (lane == 0) sbound[warp] = r;
    }
    __syncthreads();

    // ---- Layer 1: qr owns k in [qr*32, qr*32+32) ----
    float acc[GPB];
    #pragma unroll
    for (int q = 0; q < GPB; q++) acc[q] = 0.f;

    #pragma unroll
    for (int c = 0; c < 2; c++) {
        const int kb = qr * 32 + c * 16;
        float w[16];
        #pragma unroll
        for (int j = 0; j < 16; j++) w[j] = W1[(kb + j) * H + col];
        #pragma unroll
        for (int j = 0; j < 16; j += 4) {
            float4 s0 = *reinterpret_cast<const float4*>(&sS[0][kb + j]);
            float4 s1 = *reinterpret_cast<const float4*>(&sS[1][kb + j]);
            float4 s2 = *reinterpret_cast<const float4*>(&sS[2][kb + j]);
            float4 s3 = *reinterpret_cast<const float4*>(&sS[3][kb + j]);
            #pragma unroll
            for (int kk = 0; kk < 4; kk++) {
                float ww = w[j + kk];
                acc[0] = fmaf((&s0.x)[kk], ww, acc[0]);
                acc[1] = fmaf((&s1.x)[kk], ww, acc[1]);
                acc[2] = fmaf((&s2.x)[kk], ww, acc[2]);
                acc[3] = fmaf((&s3.x)[kk], ww, acc[3]);
            }
        }
    }
    #pragma unroll
    for (int q = 0; q < GPB; q++) sP[qr][q][col] = acc[q];
    __syncthreads();

    {
        int q = t >> 8, c = t & (H - 1);
        float cnt = (float)(sbound[q + 1] - sbound[q]);
        float h = b1[c] + sP[0][q][c] + sP[1][q][c] + sP[2][q][c] + sP[3][q][c];
        sH[q][c] = fmaxf(h, 0.f) * cnt;
    }
    __syncthreads();

    // ---- Layer 2: qr owns k in [qr*64, qr*64+64) ----
    #pragma unroll
    for (int q = 0; q < GPB; q++) acc[q] = 0.f;

    #pragma unroll
    for (int c = 0; c < 4; c++) {
        const int kb = qr * 64 + c * 16;
        float w[16];
        #pragma unroll
        for (int j = 0; j < 16; j++) w[j] = W2[(kb + j) * H + col];
        #pragma unroll
        for (int j = 0; j < 16; j += 4) {
            float4 s0 = *reinterpret_cast<const float4*>(&sH[0][kb + j]);
            float4 s1 = *reinterpret_cast<const float4*>(&sH[1][kb + j]);
            float4 s2 = *reinterpret_cast<const float4*>(&sH[2][kb + j]);
            float4 s3 = *reinterpret_cast<const float4*>(&sH[3][kb + j]);
            #pragma unroll
            for (int kk = 0; kk < 4; kk++) {
                float ww = w[j + kk];
                acc[0] = fmaf((&s0.x)[kk], ww, acc[0]);
                acc[1] = fmaf((&s1.x)[kk], ww, acc[1]);
                acc[2] = fmaf((&s2.x)[kk], ww, acc[2]);
                acc[3] = fmaf((&s3.x)[kk], ww, acc[3]);
            }
        }
    }
    #pragma unroll
    for (int q = 0; q < GPB; q++) sP[qr][q][col] = acc[q];
    __syncthreads();

    // ---- Head ----
    {
        int q = t >> 8, c = t & (H - 1);
        float h = b2[c] + sP[0][q][c] + sP[1][q][c] + sP[2][q][c] + sP[3][q][c];
        float v = fmaxf(h, 0.f) * Wc[c];
        #pragma unroll
        for (int s = 16; s > 0; s >>= 1)
            v += __shfl_down_sync(0xFFFFFFFFu, v, s);
        if (lane == 0) sRed[q][warp & 7] = v;
    }
    __syncthreads();

    if (t < GPB) {
        float c = bc[0];
        #pragma unroll
        for (int w = 0; w < 8; w++) c += sRed[t][w];
        float sp = fmaxf(c, 0.f) + log1pf(expf(-fabsf(c)));
        sv[t] = sp / (1.f + sp);
    }
    __syncthreads();

    const int lo = sbound[0], hi = sbound[GPB];
    for (int n = lo + t; n < hi; n += MLP_T)
        out[n] = sv[batch[n] - g0];
}

// ---------------------------------------------------------------------------
extern "C" void kernel_launch(void* const* d_in, const int* in_sizes, int n_in,
                              void* d_out, int out_size) {
    const float* x     = (const float*)d_in[0];
    const int*   batch = (const int*)d_in[1];
    const float* W1    = (const float*)d_in[2];
    const float* b1    = (const float*)d_in[3];
    const float* W2    = (const float*)d_in[4];
    const float* b2    = (const float*)d_in[5];
    const float* Wc    = (const float*)d_in[6];
    const float* bc    = (const float*)d_in[7];
    float*       out   = (float*)d_out;

    const int N = in_sizes[1];

    int segBlocks = (N + SEG_RPB - 1) / SEG_RPB;
    segsum_kernel<<<segBlocks, SEG_T>>>(
        reinterpret_cast<const float4*>(x), batch, N);

    mlp_kernel<<<NUM_GRAPHS / GPB, MLP_T>>>(batch, N, W1, b1, W2, b2, Wc, bc, out);
}

// round 9
// speedup vs baseline: 1.3249x; 1.3249x over previous
#include <cuda_runtime.h>

#define NUM_GRAPHS 512
#define D 128
#define H 256
#define GPB 4             // graphs per MLP block
#define MLP_T 1024        // 256 cols x 4 K-quarters

#define SEG_T 512         // segsum threads per block (16 warps), 1 block/graph

// Scratch (allocation-free rule): __device__ globals.
// g_S fully overwritten by segsum each run (direct stores, no accumulate),
// g_lo fully overwritten each run -> no cross-replay state.
__device__ float g_S[NUM_GRAPHS * D];
__device__ int   g_lo[NUM_GRAPHS + 1];

// ---------------------------------------------------------------------------
__device__ __forceinline__ void facc(float4& a, float4 v) {
    a.x += v.x; a.y += v.y; a.z += v.z; a.w += v.w;
}

// Warp-cooperative lower_bound on sorted int array: 32-ary search, ~4 rounds.
__device__ __forceinline__ int warp_lower_bound(const int* __restrict__ a,
                                                int n, int v, int lane) {
    int lo = 0, hi = n;
    while (hi - lo > 32) {
        int span = hi - lo;
        int idx = lo + (int)(((long long)span * lane) >> 5);
        int av = a[idx];
        unsigned m = __ballot_sync(0xFFFFFFFFu, av < v);
        int c = __popc(m);
        int nlo = (c > 0) ? lo + (int)(((long long)span * (c - 1)) >> 5) + 1 : lo;
        int nhi = (c < 32) ? lo + (int)(((long long)span * c) >> 5) : hi;
        lo = nlo; hi = nhi;
    }
    int idx = lo + lane;
    bool lt = (idx < hi) ? (a[idx] < v) : false;
    unsigned m = __ballot_sync(0xFFFFFFFFu, lt);
    return lo + __popc(m);
}

// Segment sum, one block per graph. Rows of graph g are the contiguous range
// [lb(g), lb(g+1)) because batch is sorted. 16 warps stride the range
// (warp-stride 16 rows), lane owns one float4 column chunk, 4-deep load
// batches. Cross-warp smem reduce, then ONE direct (non-atomic) store.
__global__ __launch_bounds__(SEG_T) void segsum_kernel(
        const float4* __restrict__ x4, const int* __restrict__ batch, int N) {
    __shared__ int   sb[2];
    __shared__ float sAcc[16][D + 1];    // +1 pad: conflict-free column reads

    const int g    = blockIdx.x;
    const int t    = threadIdx.x;
    const int lane = t & 31;
    const int warp = t >> 5;             // 0..15

    // Bounds: warp 0 -> lb(g), warp 1 -> lb(g+1), in parallel.
    if (warp < 2) {
        int r = warp_lower_bound(batch, N, g + warp, lane);
        if (lane == 0) sb[warp] = r;
    }
    __syncthreads();
    const int lo = sb[0], hi = sb[1];

    // Publish bounds for mlp_kernel.
    if (t == 0) {
        g_lo[g] = lo;
        if (g == NUM_GRAPHS - 1) g_lo[NUM_GRAPHS] = hi;
    }

    // Accumulate rows lo+warp, lo+warp+16, ... in 4-deep batches.
    float4 a0 = make_float4(0.f, 0.f, 0.f, 0.f);
    float4 a1 = a0, a2 = a0, a3 = a0;
    int r = lo + warp;
    for (; r + 48 < hi; r += 64) {
        float4 v0 = x4[(size_t)(r +  0) * (D / 4) + lane];
        float4 v1 = x4[(size_t)(r + 16) * (D / 4) + lane];
        float4 v2 = x4[(size_t)(r + 32) * (D / 4) + lane];
        float4 v3 = x4[(size_t)(r + 48) * (D / 4) + lane];
        facc(a0, v0); facc(a1, v1); facc(a2, v2); facc(a3, v3);
    }
    for (; r < hi; r += 16)
        facc(a0, x4[(size_t)r * (D / 4) + lane]);
    facc(a0, a1); facc(a2, a3); facc(a0, a2);

    sAcc[warp][lane * 4 + 0] = a0.x;
    sAcc[warp][lane * 4 + 1] = a0.y;
    sAcc[warp][lane * 4 + 2] = a0.z;
    sAcc[warp][lane * 4 + 3] = a0.w;
    __syncthreads();

    // 128 threads reduce 16 warp-partials per column; direct store (no atomics).
    if (t < D) {
        float v = 0.f;
        #pragma unroll
        for (int w = 0; w < 16; w++) v += sAcc[w][t];
        g_S[g * D + t] = v;
    }
}

// ---------------------------------------------------------------------------
// Per-graph MLP + fused scatter. 1024 threads: col = t&255, K-quarter
// qr = t>>8. Weights gmem->registers (coalesced 16-deep batches), activations
// via LDS.128, one partial-combine per layer. Bounds come precomputed in g_lo.
__global__ __launch_bounds__(MLP_T) void mlp_kernel(
        const int* __restrict__ batch, int N,
        const float* __restrict__ W1, const float* __restrict__ b1,
        const float* __restrict__ W2, const float* __restrict__ b2,
        const float* __restrict__ Wc, const float* __restrict__ bc,
        float* __restrict__ out) {
    __shared__ float sS[GPB][D];
    __shared__ float sH[GPB][H];
    __shared__ float sP[4][GPB][H];
    __shared__ float sRed[GPB][8];
    __shared__ int   sbound[GPB + 1];
    __shared__ float sv[GPB];

    const int g0   = blockIdx.x * GPB;
    const int t    = threadIdx.x;
    const int col  = t & (H - 1);
    const int qr   = t >> 8;
    const int lane = t & 31;
    const int warp = t >> 5;

    if (t < GPB * D)
        sS[t / D][t % D] = g_S[g0 * D + t];
    if (t <= GPB)
        sbound[t] = g_lo[g0 + t];
    __syncthreads();

    // ---- Layer 1: qr owns k in [qr*32, qr*32+32) ----
    float acc[GPB];
    #pragma unroll
    for (int q = 0; q < GPB; q++) acc[q] = 0.f;

    #pragma unroll
    for (int c = 0; c < 2; c++) {
        const int kb = qr * 32 + c * 16;
        float w[16];
        #pragma unroll
        for (int j = 0; j < 16; j++) w[j] = W1[(kb + j) * H + col];
        #pragma unroll
        for (int j = 0; j < 16; j += 4) {
            float4 s0 = *reinterpret_cast<const float4*>(&sS[0][kb + j]);
            float4 s1 = *reinterpret_cast<const float4*>(&sS[1][kb + j]);
            float4 s2 = *reinterpret_cast<const float4*>(&sS[2][kb + j]);
            float4 s3 = *reinterpret_cast<const float4*>(&sS[3][kb + j]);
            #pragma unroll
            for (int kk = 0; kk < 4; kk++) {
                float ww = w[j + kk];
                acc[0] = fmaf((&s0.x)[kk], ww, acc[0]);
                acc[1] = fmaf((&s1.x)[kk], ww, acc[1]);
                acc[2] = fmaf((&s2.x)[kk], ww, acc[2]);
                acc[3] = fmaf((&s3.x)[kk], ww, acc[3]);
            }
        }
    }
    #pragma unroll
    for (int q = 0; q < GPB; q++) sP[qr][q][col] = acc[q];
    __syncthreads();

    // combine quarters -> h1 = relu(b1 + Σp) * cnt  (cnt scale = agg2)
    {
        int q = t >> 8, c = t & (H - 1);
        float cnt = (float)(sbound[q + 1] - sbound[q]);
        float h = b1[c] + sP[0][q][c] + sP[1][q][c] + sP[2][q][c] + sP[3][q][c];
        sH[q][c] = fmaxf(h, 0.f) * cnt;
    }
    __syncthreads();

    // ---- Layer 2: qr owns k in [qr*64, qr*64+64) ----
    #pragma unroll
    for (int q = 0; q < GPB; q++) acc[q] = 0.f;

    #pragma unroll
    for (int c = 0; c < 4; c++) {
        const int kb = qr * 64 + c * 16;
        float w[16];
        #pragma unroll
        for (int j = 0; j < 16; j++) w[j] = W2[(kb + j) * H + col];
        #pragma unroll
        for (int j = 0; j < 16; j += 4) {
            float4 s0 = *reinterpret_cast<const float4*>(&sH[0][kb + j]);
            float4 s1 = *reinterpret_cast<const float4*>(&sH[1][kb + j]);
            float4 s2 = *reinterpret_cast<const float4*>(&sH[2][kb + j]);
            float4 s3 = *reinterpret_cast<const float4*>(&sH[3][kb + j]);
            #pragma unroll
            for (int kk = 0; kk < 4; kk++) {
                float ww = w[j + kk];
                acc[0] = fmaf((&s0.x)[kk], ww, acc[0]);
                acc[1] = fmaf((&s1.x)[kk], ww, acc[1]);
                acc[2] = fmaf((&s2.x)[kk], ww, acc[2]);
                acc[3] = fmaf((&s3.x)[kk], ww, acc[3]);
            }
        }
    }
    #pragma unroll
    for (int q = 0; q < GPB; q++) sP[qr][q][col] = acc[q];
    __syncthreads();

    // ---- Head: h2 = relu(b2 + Σp); c = Σ_col h2*Wc; softplus-sigmoid ----
    {
        int q = t >> 8, c = t & (H - 1);
        float h = b2[c] + sP[0][q][c] + sP[1][q][c] + sP[2][q][c] + sP[3][q][c];
        float v = fmaxf(h, 0.f) * Wc[c];
        #pragma unroll
        for (int s = 16; s > 0; s >>= 1)
            v += __shfl_down_sync(0xFFFFFFFFu, v, s);
        if (lane == 0) sRed[q][warp & 7] = v;
    }
    __syncthreads();

    if (t < GPB) {
        float c = bc[0];
        #pragma unroll
        for (int w = 0; w < 8; w++) c += sRed[t][w];
        float sp = fmaxf(c, 0.f) + log1pf(expf(-fabsf(c)));
        sv[t] = sp / (1.f + sp);
    }
    __syncthreads();

    // ---- Fused scatter over this block's contiguous node range ----
    const int lo = sbound[0], hi = sbound[GPB];
    for (int n = lo + t; n < hi; n += MLP_T)
        out[n] = sv[batch[n] - g0];
}

// ---------------------------------------------------------------------------
extern "C" void kernel_launch(void* const* d_in, const int* in_sizes, int n_in,
                              void* d_out, int out_size) {
    const float* x     = (const float*)d_in[0];
    const int*   batch = (const int*)d_in[1];
    const float* W1    = (const float*)d_in[2];
    const float* b1    = (const float*)d_in[3];
    const float* W2    = (const float*)d_in[4];
    const float* b2    = (const float*)d_in[5];
    const float* Wc    = (const float*)d_in[6];
    const float* bc    = (const float*)d_in[7];
    float*       out   = (float*)d_out;

    const int N = in_sizes[1];

    segsum_kernel<<<NUM_GRAPHS, SEG_T>>>(
        reinterpret_cast<const float4*>(x), batch, N);

    mlp_kernel<<<NUM_GRAPHS / GPB, MLP_T>>>(batch, N, W1, b1, W2, b2, Wc, bc, out);
}

// round 10
// speedup vs baseline: 1.4663x; 1.1067x over previous
#include <cuda_runtime.h>

#define NUM_GRAPHS 512
#define D 128
#define H 256
#define GPB 4             // graphs per block
#define T 1024            // threads per block (32 warps)

// ---------------------------------------------------------------------------
__device__ __forceinline__ void facc(float4& a, float4 v) {
    a.x += v.x; a.y += v.y; a.z += v.z; a.w += v.w;
}

// Warp-cooperative lower_bound on sorted int array: 32-ary search, ~4 rounds.
__device__ __forceinline__ int warp_lower_bound(const int* __restrict__ a,
                                                int n, int v, int lane) {
    int lo = 0, hi = n;
    while (hi - lo > 32) {
        int span = hi - lo;
        int idx = lo + (int)(((long long)span * lane) >> 5);
        int av = a[idx];
        unsigned m = __ballot_sync(0xFFFFFFFFu, av < v);
        int c = __popc(m);
        int nlo = (c > 0) ? lo + (int)(((long long)span * (c - 1)) >> 5) + 1 : lo;
        int nhi = (c < 32) ? lo + (int)(((long long)span * c) >> 5) : hi;
        lo = nlo; hi = nhi;
    }
    int idx = lo + lane;
    bool lt = (idx < hi) ? (a[idx] < v) : false;
    unsigned m = __ballot_sync(0xFFFFFFFFu, lt);
    return lo + __popc(m);
}

// ---------------------------------------------------------------------------
// ONE kernel: per-block segment-sum of its own 4 graphs (contiguous rows of x
// because batch is sorted) -> 2-layer MLP on the 4 graph vectors -> confidence
// head -> scatter to all nodes of those graphs. No global scratch.
__global__ __launch_bounds__(T) void fused_kernel(
        const float4* __restrict__ x4, const int* __restrict__ batch, int N,
        const float* __restrict__ W1, const float* __restrict__ b1,
        const float* __restrict__ W2, const float* __restrict__ b2,
        const float* __restrict__ Wc, const float* __restrict__ bc,
        float* __restrict__ out) {
    // sBuf: phase 1 = 32 warp-partial rows [32][128]; phase 2 = sP [4][4][256]
    __shared__ float sBuf[4096];                     // 16 KB
    __shared__ float sS[GPB][D];                     // 2 KB  per-graph sums
    __shared__ float sH[GPB][H];                     // 4 KB  h1
    __shared__ float sRed[GPB][8];
    __shared__ int   sbound[GPB + 1];
    __shared__ float sv[GPB];

    const int g0   = blockIdx.x * GPB;
    const int t    = threadIdx.x;
    const int col  = t & (H - 1);
    const int qr   = t >> 8;
    const int lane = t & 31;
    const int warp = t >> 5;            // 0..31

    // ---- Bounds: warps 0..4 search lb(g0)..lb(g0+4) in parallel ----
    if (warp <= GPB) {
        int r = warp_lower_bound(batch, N, g0 + warp, lane);
        if (lane == 0) sbound[warp] = r;
    }
    __syncthreads();

    // ---- Segment sum: 8 warps per graph; warp sub-stride 8 rows; lane owns
    //      one float4 column chunk; 4-deep independent load batches ----
    {
        const int q   = warp >> 3;      // graph 0..3
        const int sub = warp & 7;       // 0..7
        const int lo = sbound[q], hi = sbound[q + 1];

        float4 a0 = make_float4(0.f, 0.f, 0.f, 0.f);
        float4 a1 = a0, a2 = a0, a3 = a0;
        int r = lo + sub;
        for (; r + 24 < hi; r += 32) {
            float4 v0 = x4[(size_t)(r +  0) * (D / 4) + lane];
            float4 v1 = x4[(size_t)(r +  8) * (D / 4) + lane];
            float4 v2 = x4[(size_t)(r + 16) * (D / 4) + lane];
            float4 v3 = x4[(size_t)(r + 24) * (D / 4) + lane];
            facc(a0, v0); facc(a1, v1); facc(a2, v2); facc(a3, v3);
        }
        for (; r < hi; r += 8)
            facc(a0, x4[(size_t)r * (D / 4) + lane]);
        facc(a0, a1); facc(a2, a3); facc(a0, a2);

        *reinterpret_cast<float4*>(&sBuf[warp * D + lane * 4]) = a0;
    }
    __syncthreads();

    // Reduce 8 warp-partials per graph -> sS (512 threads, 1 col each)
    if (t < GPB * D) {
        const int q = t >> 7, c = t & (D - 1);
        float v = 0.f;
        #pragma unroll
        for (int w = 0; w < 8; w++) v += sBuf[(q * 8 + w) * D + c];
        sS[q][c] = v;
    }
    __syncthreads();

    float* sP = sBuf;   // reuse as [4 quarters][GPB][H]

    // ---- Layer 1: qr owns k in [qr*32, qr*32+32) ----
    float acc[GPB];
    #pragma unroll
    for (int q = 0; q < GPB; q++) acc[q] = 0.f;

    #pragma unroll
    for (int c = 0; c < 2; c++) {
        const int kb = qr * 32 + c * 16;
        float w[16];
        #pragma unroll
        for (int j = 0; j < 16; j++) w[j] = W1[(kb + j) * H + col];
        #pragma unroll
        for (int j = 0; j < 16; j += 4) {
            float4 s0 = *reinterpret_cast<const float4*>(&sS[0][kb + j]);
            float4 s1 = *reinterpret_cast<const float4*>(&sS[1][kb + j]);
            float4 s2 = *reinterpret_cast<const float4*>(&sS[2][kb + j]);
            float4 s3 = *reinterpret_cast<const float4*>(&sS[3][kb + j]);
            #pragma unroll
            for (int kk = 0; kk < 4; kk++) {
                float ww = w[j + kk];
                acc[0] = fmaf((&s0.x)[kk], ww, acc[0]);
                acc[1] = fmaf((&s1.x)[kk], ww, acc[1]);
                acc[2] = fmaf((&s2.x)[kk], ww, acc[2]);
                acc[3] = fmaf((&s3.x)[kk], ww, acc[3]);
            }
        }
    }
    #pragma unroll
    for (int q = 0; q < GPB; q++) sP[(qr * GPB + q) * H + col] = acc[q];
    __syncthreads();

    // combine quarters -> h1 = relu(b1 + Σp) * cnt  (cnt scale = agg2)
    {
        int q = t >> 8, c = t & (H - 1);
        float cnt = (float)(sbound[q + 1] - sbound[q]);
        float h = b1[c] + sP[(0 * GPB + q) * H + c] + sP[(1 * GPB + q) * H + c]
                        + sP[(2 * GPB + q) * H + c] + sP[(3 * GPB + q) * H + c];
        sH[q][c] = fmaxf(h, 0.f) * cnt;
    }
    __syncthreads();

    // ---- Layer 2: qr owns k in [qr*64, qr*64+64) ----
    #pragma unroll
    for (int q = 0; q < GPB; q++) acc[q] = 0.f;

    #pragma unroll
    for (int c = 0; c < 4; c++) {
        const int kb = qr * 64 + c * 16;
        float w[16];
        #pragma unroll
        for (int j = 0; j < 16; j++) w[j] = W2[(kb + j) * H + col];
        #pragma unroll
        for (int j = 0; j < 16; j += 4) {
            float4 s0 = *reinterpret_cast<const float4*>(&sH[0][kb + j]);
            float4 s1 = *reinterpret_cast<const float4*>(&sH[1][kb + j]);
            float4 s2 = *reinterpret_cast<const float4*>(&sH[2][kb + j]);
            float4 s3 = *reinterpret_cast<const float4*>(&sH[3][kb + j]);
            #pragma unroll
            for (int kk = 0; kk < 4; kk++) {
                float ww = w[j + kk];
                acc[0] = fmaf((&s0.x)[kk], ww, acc[0]);
                acc[1] = fmaf((&s1.x)[kk], ww, acc[1]);
                acc[2] = fmaf((&s2.x)[kk], ww, acc[2]);
                acc[3] = fmaf((&s3.x)[kk], ww, acc[3]);
            }
        }
    }
    #pragma unroll
    for (int q = 0; q < GPB; q++) sP[(qr * GPB + q) * H + col] = acc[q];
    __syncthreads();

    // ---- Head: h2 = relu(b2 + Σp); c = Σ_col h2*Wc; softplus-sigmoid ----
    {
        int q = t >> 8, c = t & (H - 1);
        float h = b2[c] + sP[(0 * GPB + q) * H + c] + sP[(1 * GPB + q) * H + c]
                        + sP[(2 * GPB + q) * H + c] + sP[(3 * GPB + q) * H + c];
        float v = fmaxf(h, 0.f) * Wc[c];
        #pragma unroll
        for (int s = 16; s > 0; s >>= 1)
            v += __shfl_down_sync(0xFFFFFFFFu, v, s);
        if (lane == 0) sRed[q][warp & 7] = v;
    }
    __syncthreads();

    if (t < GPB) {
        float c = bc[0];
        #pragma unroll
        for (int w = 0; w < 8; w++) c += sRed[t][w];
        float sp = fmaxf(c, 0.f) + log1pf(expf(-fabsf(c)));
        sv[t] = sp / (1.f + sp);
    }
    __syncthreads();

    // ---- Scatter over this block's contiguous node range ----
    const int lo = sbound[0], hi = sbound[GPB];
    for (int n = lo + t; n < hi; n += T)
        out[n] = sv[batch[n] - g0];
}

// ---------------------------------------------------------------------------
extern "C" void kernel_launch(void* const* d_in, const int* in_sizes, int n_in,
                              void* d_out, int out_size) {
    const float* x     = (const float*)d_in[0];
    const int*   batch = (const int*)d_in[1];
    const float* W1    = (const float*)d_in[2];
    const float* b1    = (const float*)d_in[3];
    const float* W2    = (const float*)d_in[4];
    const float* b2    = (const float*)d_in[5];
    const float* Wc    = (const float*)d_in[6];
    const float* bc    = (const float*)d_in[7];
    float*       out   = (float*)d_out;

    const int N = in_sizes[1];

    fused_kernel<<<NUM_GRAPHS / GPB, T>>>(
        reinterpret_cast<const float4*>(x), batch, N,
        W1, b1, W2, b2, Wc, bc, out);
}